// round 9
// baseline (speedup 1.0000x reference)
#include <cuda_runtime.h>
#include <cuda_bf16.h>

#define N_NODES 10000
#define NQUERY  65536

__device__ float g_P2[N_NODES];   // |position[i]|^2, rebuilt every launch

__global__ __launch_bounds__(256)
void p2_kernel(const float* __restrict__ position)
{
    const int node = (blockIdx.x * blockDim.x + threadIdx.x) >> 5;
    const int lane = threadIdx.x & 31;
    if (node >= N_NODES) return;
    const float4 p = __ldg(&((const float4*)position)[node * 32 + lane]);
    float s = p.x * p.x + p.y * p.y + p.z * p.z + p.w * p.w;
    #pragma unroll
    for (int o = 16; o > 0; o >>= 1)
        s += __shfl_xor_sync(0xFFFFFFFFu, s, o);
    if (lane == 0) g_P2[node] = s;
}

__global__ __launch_bounds__(256, 5)
void madgraph_kernel(const int* __restrict__ src,
                     const int* __restrict__ dst,
                     const int* __restrict__ mid0,
                     const int* __restrict__ mid1,
                     const float* __restrict__ position,
                     const float* __restrict__ src_field,
                     const float* __restrict__ dst_field,
                     const float* __restrict__ unc,
                     const float* __restrict__ edge,
                     float* __restrict__ out)
{
    const unsigned FULL = 0xFFFFFFFFu;
    const int warp = (blockIdx.x * blockDim.x + threadIdx.x) >> 5;
    const int lane = threadIdx.x & 31;
    const int n = warp;

    const int s_node = __ldg(&src[n]);
    const int d_node = __ldg(&dst[n]);

    // Lane l<8 holds mid0[n][l]; lanes 8..15 hold mid1[n][l-8].
    int m_own = 0;
    if (lane < 8)        m_own = __ldg(&mid0[n * 8 + lane]);
    else if (lane < 16)  m_own = __ldg(&mid1[n * 8 + (lane - 8)]);

    // Scattered loads that only depend on indices — issue ASAP.
    float ev_own = 0.f, p2m_own = 0.f;
    if (lane < 16) {
        const int eidx = (lane < 8) ? (m_own * N_NODES + d_node)    // edge[mid0[s], dst]
                                    : (s_node * N_NODES + m_own);   // edge[src, mid1[s]]
        ev_own  = __ldg(&edge[eidx]);
        p2m_own = g_P2[m_own];            // 40KB table, L1-hot
    }
    const float u    = __ldg(unc);
    const float p2s  = g_P2[s_node];
    const float p2d  = g_P2[d_node];

    const float4* pos4 = (const float4*)position;
    const float4* sf4  = (const float4*)src_field;
    const float4* df4  = (const float4*)dst_field;

    float D1, D2;          // lane<16: pm·f ; lane>=16: pm·base  (per pass)
    float psf1_p, psf2_p;  // per-lane partials of ps·fd and pd·fs

    // ---- pass 1: samples 0..7 (base = pos[src], field = dst_field[dst]) ----
    {
        const float4 base = __ldg(&pos4[s_node * 32 + lane]);
        const float4 f    = __ldg(&df4 [d_node * 32 + lane]);
        psf1_p = base.x * f.x + base.y * f.y + base.z * f.z + base.w * f.w;
        int mm[8];
        #pragma unroll
        for (int s = 0; s < 8; ++s) mm[s] = __shfl_sync(FULL, m_own, s);
        float4 pm[8];
        #pragma unroll
        for (int s = 0; s < 8; ++s) pm[s] = __ldg(&pos4[mm[s] * 32 + lane]);
        float V[16];
        #pragma unroll
        for (int s = 0; s < 8; ++s) {
            V[s]     = pm[s].x * f.x    + pm[s].y * f.y    + pm[s].z * f.z    + pm[s].w * f.w;
            V[8 + s] = pm[s].x * base.x + pm[s].y * base.y + pm[s].z * base.z + pm[s].w * base.w;
        }
        #pragma unroll
        for (int m = 16, cnt = 16; m >= 2; m >>= 1, cnt >>= 1) {
            const int  half  = cnt >> 1;
            const bool upper = (lane & m) != 0;
            #pragma unroll
            for (int j = 0; j < 8; ++j) {
                if (j < half) {
                    float send = upper ? V[j] : V[j + half];
                    float recv = __shfl_xor_sync(FULL, send, m);
                    V[j] = (upper ? V[j + half] : V[j]) + recv;
                }
            }
        }
        D1 = V[0] + __shfl_xor_sync(FULL, V[0], 1);
    }

    // ---- pass 2: samples 8..15 (base = pos[dst], field = src_field[src]) ----
    {
        const float4 base = __ldg(&pos4[d_node * 32 + lane]);
        const float4 f    = __ldg(&sf4 [s_node * 32 + lane]);
        psf2_p = base.x * f.x + base.y * f.y + base.z * f.z + base.w * f.w;
        int mm[8];
        #pragma unroll
        for (int s = 0; s < 8; ++s) mm[s] = __shfl_sync(FULL, m_own, 8 + s);
        float4 pm[8];
        #pragma unroll
        for (int s = 0; s < 8; ++s) pm[s] = __ldg(&pos4[mm[s] * 32 + lane]);
        float V[16];
        #pragma unroll
        for (int s = 0; s < 8; ++s) {
            V[s]     = pm[s].x * f.x    + pm[s].y * f.y    + pm[s].z * f.z    + pm[s].w * f.w;
            V[8 + s] = pm[s].x * base.x + pm[s].y * base.y + pm[s].z * base.z + pm[s].w * base.w;
        }
        #pragma unroll
        for (int m = 16, cnt = 16; m >= 2; m >>= 1, cnt >>= 1) {
            const int  half  = cnt >> 1;
            const bool upper = (lane & m) != 0;
            #pragma unroll
            for (int j = 0; j < 8; ++j) {
                if (j < half) {
                    float send = upper ? V[j] : V[j + half];
                    float recv = __shfl_xor_sync(FULL, send, m);
                    V[j] = (upper ? V[j + half] : V[j]) + recv;
                }
            }
        }
        D2 = V[0] + __shfl_xor_sync(FULL, V[0], 1);
    }

    // Combined 2-value reduce of the base dots: stage 16 separates,
    // stages 8..1 allreduce within halves. Lanes<16 end with psf1, >=16 with psf2.
    {
        const bool up = (lane & 16) != 0;
        float send = up ? psf1_p : psf2_p;
        float keep = up ? psf2_p : psf1_p;
        float r = keep + __shfl_xor_sync(FULL, send, 16);
        #pragma unroll
        for (int o = 8; o > 0; o >>= 1)
            r += __shfl_xor_sync(FULL, r, o);
        psf1_p = r;                                   // own half's value
        psf2_p = __shfl_xor_sync(FULL, r, 16);        // other half's value
    }
    // lanes<16: psf1_p = ps·fd, psf2_p = pd·fs

    // Lanes 16..31 hold the pm·base dots; hand to lanes 0..15.
    const float Y1 = __shfl_xor_sync(FULL, D1, 16);
    const float Y2 = __shfl_xor_sync(FULL, D2, 16);

    // Slot layout: even lanes (<16) own pass-1 sample (l>>1); odd own pass-2 sample 8+(l>>1).
    const int  odd  = lane & 1;
    const int  samp = (lane >> 1) | (odd ? 8 : 0);
    const float ev  = __shfl_sync(FULL, ev_own,  samp);
    const float p2m = __shfl_sync(FULL, p2m_own, samp);

    float a, logit;
    if (lane < 16) {
        const float psf  = odd ? psf2_p : psf1_p;
        const float p2b  = odd ? p2d    : p2s;
        const float X    = odd ? D2 : D1;    // pm·f
        const float Y    = odd ? Y2 : Y1;    // pm·base
        logit = (psf - X) + u * ev;
        const float n2 = fmaxf(p2b - 2.0f * Y + p2m, 0.0f);
        a = 1.0f - sqrtf(n2);
    } else {
        logit = 0.f;
        a = -1e30f;
    }

    // 16-wide softmax among lanes 0..15
    float mx = a;
    #pragma unroll
    for (int o = 8; o > 0; o >>= 1)
        mx = fmaxf(mx, __shfl_xor_sync(FULL, mx, o));

    const float e = (lane < 16) ? __expf(a - mx) : 0.f;
    float num = logit * e;
    float den = e;
    #pragma unroll
    for (int o = 8; o > 0; o >>= 1) {
        num += __shfl_xor_sync(FULL, num, o);
        den += __shfl_xor_sync(FULL, den, o);
    }

    if (lane == 0) out[n] = num / den;
}

extern "C" void kernel_launch(void* const* d_in, const int* in_sizes, int n_in,
                              void* d_out, int out_size)
{
    const int*   src      = (const int*)  d_in[0];
    const int*   dst      = (const int*)  d_in[1];
    const int*   mid0     = (const int*)  d_in[2];
    const int*   mid1     = (const int*)  d_in[3];
    const float* position = (const float*)d_in[4];
    const float* src_f    = (const float*)d_in[5];
    const float* dst_f    = (const float*)d_in[6];
    const float* unc      = (const float*)d_in[7];
    const float* edge     = (const float*)d_in[8];
    float*       out      = (float*)      d_out;

    // Prologue: per-node squared norms (stream-ordered before the main kernel).
    p2_kernel<<<(N_NODES * 32 + 255) / 256, 256>>>(position);

    const int blocks = NQUERY / 8;   // 8 warps (queries) per 256-thread block
    madgraph_kernel<<<blocks, 256>>>(src, dst, mid0, mid1, position,
                                     src_f, dst_f, unc, edge, out);
}

// round 10
// speedup vs baseline: 1.1033x; 1.1033x over previous
#include <cuda_runtime.h>
#include <cuda_bf16.h>

#define N_NODES 10000
#define NQUERY  65536

#define GRID_BLOCKS 740          // ~148 SMs x 5 resident CTAs
#define WARPS_TOTAL (GRID_BLOCKS * 8)

__global__ __launch_bounds__(256, 5)
void madgraph_kernel(const int* __restrict__ src,
                     const int* __restrict__ dst,
                     const int* __restrict__ mid0,
                     const int* __restrict__ mid1,
                     const float* __restrict__ position,
                     const float* __restrict__ src_field,
                     const float* __restrict__ dst_field,
                     const float* __restrict__ unc,
                     const float* __restrict__ edge,
                     float* __restrict__ out)
{
    const unsigned FULL = 0xFFFFFFFFu;
    const int gwarp = (blockIdx.x * blockDim.x + threadIdx.x) >> 5;
    const int lane  = threadIdx.x & 31;

    const float4* pos4 = (const float4*)position;
    const float4* sf4  = (const float4*)src_field;
    const float4* df4  = (const float4*)dst_field;
    const float u = __ldg(unc);

    // Carried tail state for the software pipeline (query i-1's softmax inputs).
    float a_prev = 0.f, logit_prev = 0.f;
    int   n_prev = -1;

    for (int n = gwarp; n < NQUERY; n += WARPS_TOTAL) {
        // ---- head of query n: issue index/mid loads first ----
        const int s_node = __ldg(&src[n]);
        const int d_node = __ldg(&dst[n]);

        int m_own = 0;
        if (lane < 8)        m_own = __ldg(&mid0[n * 8 + lane]);
        else if (lane < 16)  m_own = __ldg(&mid1[n * 8 + (lane - 8)]);

        // ---- previous query's tail: independent work that fills the
        //      idx/mid load latency window ----
        if (n_prev >= 0) {
            float mx = a_prev;
            #pragma unroll
            for (int o = 8; o > 0; o >>= 1)
                mx = fmaxf(mx, __shfl_xor_sync(FULL, mx, o));
            const float e = (lane < 16) ? __expf(a_prev - mx) : 0.f;
            float num = logit_prev * e;
            float den = e;
            #pragma unroll
            for (int o = 8; o > 0; o >>= 1) {
                num += __shfl_xor_sync(FULL, num, o);
                den += __shfl_xor_sync(FULL, den, o);
            }
            if (lane == 0) out[n_prev] = num / den;
        }

        // Edge value (400MB DRAM table) — issue as early as possible.
        float ev_own = 0.f;
        if (lane < 16) {
            const int eidx = (lane < 8) ? (m_own * N_NODES + d_node)
                                        : (s_node * N_NODES + m_own);
            ev_own = __ldg(&edge[eidx]);
        }

        float D1, D2;

        // ---- pass 1: samples 0..7 (base = pos[src], field = dst_field[dst]) ----
        {
            const float4 base = __ldg(&pos4[s_node * 32 + lane]);
            const float4 f    = __ldg(&df4 [d_node * 32 + lane]);
            int mm[8];
            #pragma unroll
            for (int s = 0; s < 8; ++s) mm[s] = __shfl_sync(FULL, m_own, s);
            float4 pm[8];
            #pragma unroll
            for (int s = 0; s < 8; ++s) pm[s] = __ldg(&pos4[mm[s] * 32 + lane]);
            float V[16];
            #pragma unroll
            for (int s = 0; s < 8; ++s) {
                float dx = base.x - pm[s].x, dy = base.y - pm[s].y;
                float dz = base.z - pm[s].z, dw = base.w - pm[s].w;
                V[s]     = dx * f.x + dy * f.y + dz * f.z + dw * f.w;
                V[8 + s] = dx * dx  + dy * dy  + dz * dz  + dw * dw;
            }
            #pragma unroll
            for (int m = 16, cnt = 16; m >= 2; m >>= 1, cnt >>= 1) {
                const int  half  = cnt >> 1;
                const bool upper = (lane & m) != 0;
                #pragma unroll
                for (int j = 0; j < 8; ++j) {
                    if (j < half) {
                        float send = upper ? V[j] : V[j + half];
                        float recv = __shfl_xor_sync(FULL, send, m);
                        V[j] = (upper ? V[j + half] : V[j]) + recv;
                    }
                }
            }
            D1 = V[0] + __shfl_xor_sync(FULL, V[0], 1);
        }

        // ---- pass 2: samples 8..15 (base = pos[dst], field = src_field[src]) ----
        {
            const float4 base = __ldg(&pos4[d_node * 32 + lane]);
            const float4 f    = __ldg(&sf4 [s_node * 32 + lane]);
            int mm[8];
            #pragma unroll
            for (int s = 0; s < 8; ++s) mm[s] = __shfl_sync(FULL, m_own, 8 + s);
            float4 pm[8];
            #pragma unroll
            for (int s = 0; s < 8; ++s) pm[s] = __ldg(&pos4[mm[s] * 32 + lane]);
            float V[16];
            #pragma unroll
            for (int s = 0; s < 8; ++s) {
                float dx = base.x - pm[s].x, dy = base.y - pm[s].y;
                float dz = base.z - pm[s].z, dw = base.w - pm[s].w;
                V[s]     = dx * f.x + dy * f.y + dz * f.z + dw * f.w;
                V[8 + s] = dx * dx  + dy * dy  + dz * dz  + dw * dw;
            }
            #pragma unroll
            for (int m = 16, cnt = 16; m >= 2; m >>= 1, cnt >>= 1) {
                const int  half  = cnt >> 1;
                const bool upper = (lane & m) != 0;
                #pragma unroll
                for (int j = 0; j < 8; ++j) {
                    if (j < half) {
                        float send = upper ? V[j] : V[j + half];
                        float recv = __shfl_xor_sync(FULL, send, m);
                        V[j] = (upper ? V[j + half] : V[j]) + recv;
                    }
                }
            }
            D2 = V[0] + __shfl_xor_sync(FULL, V[0], 1);
        }

        // Lanes 16..31 hold squared norms; hand them to lanes 0..15.
        const float M1 = __shfl_xor_sync(FULL, D1, 16);
        const float M2 = __shfl_xor_sync(FULL, D2, 16);

        // Even lanes (<16) own pass-1 sample (l>>1); odd own pass-2 sample 8+(l>>1).
        const int  oddl = lane & 1;
        const int  samp = (lane >> 1) | (oddl ? 8 : 0);
        const float ev  = __shfl_sync(FULL, ev_own, samp);

        if (lane < 16) {
            const float dot = oddl ? D2 : D1;
            const float n2  = oddl ? M2 : M1;
            logit_prev = dot + u * ev;
            a_prev     = 1.0f - sqrtf(n2);
        } else {
            logit_prev = 0.f;
            a_prev     = -1e30f;
        }
        n_prev = n;
    }

    // ---- drain the pipeline: final query's softmax ----
    if (n_prev >= 0) {
        float mx = a_prev;
        #pragma unroll
        for (int o = 8; o > 0; o >>= 1)
            mx = fmaxf(mx, __shfl_xor_sync(FULL, mx, o));
        const float e = (lane < 16) ? __expf(a_prev - mx) : 0.f;
        float num = logit_prev * e;
        float den = e;
        #pragma unroll
        for (int o = 8; o > 0; o >>= 1) {
            num += __shfl_xor_sync(FULL, num, o);
            den += __shfl_xor_sync(FULL, den, o);
        }
        if (lane == 0) out[n_prev] = num / den;
    }
}

extern "C" void kernel_launch(void* const* d_in, const int* in_sizes, int n_in,
                              void* d_out, int out_size)
{
    const int*   src      = (const int*)  d_in[0];
    const int*   dst      = (const int*)  d_in[1];
    const int*   mid0     = (const int*)  d_in[2];
    const int*   mid1     = (const int*)  d_in[3];
    const float* position = (const float*)d_in[4];
    const float* src_f    = (const float*)d_in[5];
    const float* dst_f    = (const float*)d_in[6];
    const float* unc      = (const float*)d_in[7];
    const float* edge     = (const float*)d_in[8];
    float*       out      = (float*)      d_out;

    madgraph_kernel<<<GRID_BLOCKS, 256>>>(src, dst, mid0, mid1, position,
                                          src_f, dst_f, unc, edge, out);
}

// round 11
// speedup vs baseline: 1.2145x; 1.1007x over previous
#include <cuda_runtime.h>
#include <cuda_fp16.h>
#include <cuda_bf16.h>

#define N_NODES 10000
#define NQUERY  65536

// fp16 copy of position[N_NODES][128], rebuilt each launch (2.56 MB, L2-resident)
__device__ __half2 g_posh[N_NODES * 64];

__global__ __launch_bounds__(256)
void cvt_kernel(const float* __restrict__ position)
{
    const int i = blockIdx.x * blockDim.x + threadIdx.x;   // one float4 per thread
    if (i < N_NODES * 32) {
        const float4 v = __ldg(&((const float4*)position)[i]);
        g_posh[i * 2 + 0] = __floats2half2_rn(v.x, v.y);
        g_posh[i * 2 + 1] = __floats2half2_rn(v.z, v.w);
    }
}

__global__ __launch_bounds__(256, 6)
void madgraph_kernel(const int* __restrict__ src,
                     const int* __restrict__ dst,
                     const int* __restrict__ mid0,
                     const int* __restrict__ mid1,
                     const float* __restrict__ position,
                     const float* __restrict__ src_field,
                     const float* __restrict__ dst_field,
                     const float* __restrict__ unc,
                     const float* __restrict__ edge,
                     float* __restrict__ out)
{
    const unsigned FULL = 0xFFFFFFFFu;
    const int warp = (blockIdx.x * blockDim.x + threadIdx.x) >> 5;
    const int lane = threadIdx.x & 31;
    const int n = warp;

    const int s_node = __ldg(&src[n]);
    const int d_node = __ldg(&dst[n]);

    // Lane l<8 holds mid0[n][l]; lanes 8..15 hold mid1[n][l-8].
    int m_own = 0;
    if (lane < 8)        m_own = __ldg(&mid0[n * 8 + lane]);
    else if (lane < 16)  m_own = __ldg(&mid1[n * 8 + (lane - 8)]);

    // Edge value (400MB DRAM table) — issue ASAP, consumed at the very end.
    float ev_own = 0.f;
    if (lane < 16) {
        const int eidx = (lane < 8) ? (m_own * N_NODES + d_node)    // edge[mid0[s], dst]
                                    : (s_node * N_NODES + m_own);   // edge[src, mid1[s]]
        ev_own = __ldg(&edge[eidx]);
    }
    const float u = __ldg(unc);

    const float4* pos4 = (const float4*)position;
    const float4* sf4  = (const float4*)src_field;
    const float4* df4  = (const float4*)dst_field;
    // fp16 midpoint rows: lane owns dims [4*lane..4*lane+3] = one uint2 (8B)
    const uint2* posh = (const uint2*)g_posh;

    float D1, D2;

    // ---- pass 1: samples 0..7 (base = pos[src] fp32, field = dst_field[dst]) ----
    {
        const float4 base = __ldg(&pos4[s_node * 32 + lane]);
        const float4 f    = __ldg(&df4 [d_node * 32 + lane]);
        int mm[8];
        #pragma unroll
        for (int s = 0; s < 8; ++s) mm[s] = __shfl_sync(FULL, m_own, s);
        uint2 pm[8];
        #pragma unroll
        for (int s = 0; s < 8; ++s) pm[s] = __ldg(&posh[mm[s] * 32 + lane]);
        float V[16];
        #pragma unroll
        for (int s = 0; s < 8; ++s) {
            const float2 p01 = __half22float2(*(const __half2*)&pm[s].x);
            const float2 p23 = __half22float2(*(const __half2*)&pm[s].y);
            const float dx = base.x - p01.x, dy = base.y - p01.y;
            const float dz = base.z - p23.x, dw = base.w - p23.y;
            V[s]     = dx * f.x + dy * f.y + dz * f.z + dw * f.w;
            V[8 + s] = dx * dx  + dy * dy  + dz * dz  + dw * dw;
        }
        #pragma unroll
        for (int m = 16, cnt = 16; m >= 2; m >>= 1, cnt >>= 1) {
            const int  half  = cnt >> 1;
            const bool upper = (lane & m) != 0;
            #pragma unroll
            for (int j = 0; j < 8; ++j) {
                if (j < half) {
                    float send = upper ? V[j] : V[j + half];
                    float recv = __shfl_xor_sync(FULL, send, m);
                    V[j] = (upper ? V[j + half] : V[j]) + recv;
                }
            }
        }
        D1 = V[0] + __shfl_xor_sync(FULL, V[0], 1);
    }

    // ---- pass 2: samples 8..15 (base = pos[dst] fp32, field = src_field[src]) ----
    {
        const float4 base = __ldg(&pos4[d_node * 32 + lane]);
        const float4 f    = __ldg(&sf4 [s_node * 32 + lane]);
        int mm[8];
        #pragma unroll
        for (int s = 0; s < 8; ++s) mm[s] = __shfl_sync(FULL, m_own, 8 + s);
        uint2 pm[8];
        #pragma unroll
        for (int s = 0; s < 8; ++s) pm[s] = __ldg(&posh[mm[s] * 32 + lane]);
        float V[16];
        #pragma unroll
        for (int s = 0; s < 8; ++s) {
            const float2 p01 = __half22float2(*(const __half2*)&pm[s].x);
            const float2 p23 = __half22float2(*(const __half2*)&pm[s].y);
            const float dx = base.x - p01.x, dy = base.y - p01.y;
            const float dz = base.z - p23.x, dw = base.w - p23.y;
            V[s]     = dx * f.x + dy * f.y + dz * f.z + dw * f.w;
            V[8 + s] = dx * dx  + dy * dy  + dz * dz  + dw * dw;
        }
        #pragma unroll
        for (int m = 16, cnt = 16; m >= 2; m >>= 1, cnt >>= 1) {
            const int  half  = cnt >> 1;
            const bool upper = (lane & m) != 0;
            #pragma unroll
            for (int j = 0; j < 8; ++j) {
                if (j < half) {
                    float send = upper ? V[j] : V[j + half];
                    float recv = __shfl_xor_sync(FULL, send, m);
                    V[j] = (upper ? V[j + half] : V[j]) + recv;
                }
            }
        }
        D2 = V[0] + __shfl_xor_sync(FULL, V[0], 1);
    }

    // Lanes 16..31 hold squared norms; hand them to lanes 0..15.
    const float M1 = __shfl_xor_sync(FULL, D1, 16);
    const float M2 = __shfl_xor_sync(FULL, D2, 16);

    // Even lanes (<16) own pass-1 sample (l>>1); odd own pass-2 sample 8+(l>>1).
    const int  odd  = lane & 1;
    const int  samp = (lane >> 1) | (odd ? 8 : 0);
    const float ev  = __shfl_sync(FULL, ev_own, samp);

    float a, logit;
    if (lane < 16) {
        const float dot = odd ? D2 : D1;
        const float n2  = odd ? M2 : M1;
        logit = dot + u * ev;
        a = 1.0f - sqrtf(n2);
    } else {
        logit = 0.f;
        a = -1e30f;
    }

    // 16-wide softmax among lanes 0..15
    float mx = a;
    #pragma unroll
    for (int o = 8; o > 0; o >>= 1)
        mx = fmaxf(mx, __shfl_xor_sync(FULL, mx, o));

    const float e = (lane < 16) ? __expf(a - mx) : 0.f;
    float num = logit * e;
    float den = e;
    #pragma unroll
    for (int o = 8; o > 0; o >>= 1) {
        num += __shfl_xor_sync(FULL, num, o);
        den += __shfl_xor_sync(FULL, den, o);
    }

    if (lane == 0) out[n] = num / den;
}

extern "C" void kernel_launch(void* const* d_in, const int* in_sizes, int n_in,
                              void* d_out, int out_size)
{
    const int*   src      = (const int*)  d_in[0];
    const int*   dst      = (const int*)  d_in[1];
    const int*   mid0     = (const int*)  d_in[2];
    const int*   mid1     = (const int*)  d_in[3];
    const float* position = (const float*)d_in[4];
    const float* src_f    = (const float*)d_in[5];
    const float* dst_f    = (const float*)d_in[6];
    const float* unc      = (const float*)d_in[7];
    const float* edge     = (const float*)d_in[8];
    float*       out      = (float*)      d_out;

    // Prologue: fp32 -> fp16 position table (stream-ordered before main kernel)
    cvt_kernel<<<(N_NODES * 32 + 255) / 256, 256>>>(position);

    const int blocks = NQUERY / 8;   // 8 warps (queries) per 256-thread block
    madgraph_kernel<<<blocks, 256>>>(src, dst, mid0, mid1, position,
                                     src_f, dst_f, unc, edge, out);
}

// round 12
// speedup vs baseline: 1.2693x; 1.0452x over previous
#include <cuda_runtime.h>
#include <cuda_fp16.h>
#include <cuda_bf16.h>

#define N_NODES 10000
#define NQUERY  65536

// fp16 copies of the three node tables, rebuilt each launch (7.5 MB, L2-resident)
__device__ __half2 g_posh[N_NODES * 64];
__device__ __half2 g_sfh [N_NODES * 64];
__device__ __half2 g_dfh [N_NODES * 64];

__global__ __launch_bounds__(256)
void cvt_kernel(const float* __restrict__ position,
                const float* __restrict__ src_field,
                const float* __restrict__ dst_field)
{
    const int i = blockIdx.x * blockDim.x + threadIdx.x;   // one float4 per thread
    if (i < N_NODES * 32) {
        float4 v = __ldg(&((const float4*)position)[i]);
        g_posh[i * 2 + 0] = __floats2half2_rn(v.x, v.y);
        g_posh[i * 2 + 1] = __floats2half2_rn(v.z, v.w);
        v = __ldg(&((const float4*)src_field)[i]);
        g_sfh[i * 2 + 0] = __floats2half2_rn(v.x, v.y);
        g_sfh[i * 2 + 1] = __floats2half2_rn(v.z, v.w);
        v = __ldg(&((const float4*)dst_field)[i]);
        g_dfh[i * 2 + 0] = __floats2half2_rn(v.x, v.y);
        g_dfh[i * 2 + 1] = __floats2half2_rn(v.z, v.w);
    }
}

__device__ __forceinline__ float4 h2f4(uint2 h)
{
    const float2 a = __half22float2(*(const __half2*)&h.x);
    const float2 b = __half22float2(*(const __half2*)&h.y);
    return make_float4(a.x, a.y, b.x, b.y);
}

__global__ __launch_bounds__(256, 6)
void madgraph_kernel(const int* __restrict__ src,
                     const int* __restrict__ dst,
                     const int* __restrict__ mid0,
                     const int* __restrict__ mid1,
                     const float* __restrict__ position,
                     const float* __restrict__ src_field,
                     const float* __restrict__ dst_field,
                     const float* __restrict__ unc,
                     const float* __restrict__ edge,
                     float* __restrict__ out)
{
    const unsigned FULL = 0xFFFFFFFFu;
    const int warp = (blockIdx.x * blockDim.x + threadIdx.x) >> 5;
    const int lane = threadIdx.x & 31;
    const int n = warp;

    const int s_node = __ldg(&src[n]);
    const int d_node = __ldg(&dst[n]);

    // Lane l<8 holds mid0[n][l]; lanes 8..15 hold mid1[n][l-8].
    int m_own = 0;
    if (lane < 8)        m_own = __ldg(&mid0[n * 8 + lane]);
    else if (lane < 16)  m_own = __ldg(&mid1[n * 8 + (lane - 8)]);

    // Edge value (400MB DRAM table): evict-first so it never displaces the
    // hot fp16 tables in L2. Issue ASAP; consumed at the very end.
    float ev_own = 0.f;
    if (lane < 16) {
        const int eidx = (lane < 8) ? (m_own * N_NODES + d_node)    // edge[mid0[s], dst]
                                    : (s_node * N_NODES + m_own);   // edge[src, mid1[s]]
        ev_own = __ldcs(&edge[eidx]);
    }
    const float u = __ldg(unc);

    // fp16 rows: lane owns dims [4*lane..4*lane+3] = one uint2 (8B)
    const uint2* posh = (const uint2*)g_posh;
    const uint2* sfh  = (const uint2*)g_sfh;
    const uint2* dfh  = (const uint2*)g_dfh;

    float D1, D2;

    // ---- pass 1: samples 0..7 (base = pos[src], field = dst_field[dst]) ----
    {
        const float4 base = h2f4(posh[s_node * 32 + lane]);
        const float4 f    = h2f4(dfh [d_node * 32 + lane]);
        int mm[8];
        #pragma unroll
        for (int s = 0; s < 8; ++s) mm[s] = __shfl_sync(FULL, m_own, s);
        uint2 pm[8];
        #pragma unroll
        for (int s = 0; s < 8; ++s) pm[s] = posh[mm[s] * 32 + lane];
        float V[16];
        #pragma unroll
        for (int s = 0; s < 8; ++s) {
            const float4 p = h2f4(pm[s]);
            const float dx = base.x - p.x, dy = base.y - p.y;
            const float dz = base.z - p.z, dw = base.w - p.w;
            V[s]     = dx * f.x + dy * f.y + dz * f.z + dw * f.w;
            V[8 + s] = dx * dx  + dy * dy  + dz * dz  + dw * dw;
        }
        #pragma unroll
        for (int m = 16, cnt = 16; m >= 2; m >>= 1, cnt >>= 1) {
            const int  half  = cnt >> 1;
            const bool upper = (lane & m) != 0;
            #pragma unroll
            for (int j = 0; j < 8; ++j) {
                if (j < half) {
                    float send = upper ? V[j] : V[j + half];
                    float recv = __shfl_xor_sync(FULL, send, m);
                    V[j] = (upper ? V[j + half] : V[j]) + recv;
                }
            }
        }
        D1 = V[0] + __shfl_xor_sync(FULL, V[0], 1);
    }

    // ---- pass 2: samples 8..15 (base = pos[dst], field = src_field[src]) ----
    {
        const float4 base = h2f4(posh[d_node * 32 + lane]);
        const float4 f    = h2f4(sfh [s_node * 32 + lane]);
        int mm[8];
        #pragma unroll
        for (int s = 0; s < 8; ++s) mm[s] = __shfl_sync(FULL, m_own, 8 + s);
        uint2 pm[8];
        #pragma unroll
        for (int s = 0; s < 8; ++s) pm[s] = posh[mm[s] * 32 + lane];
        float V[16];
        #pragma unroll
        for (int s = 0; s < 8; ++s) {
            const float4 p = h2f4(pm[s]);
            const float dx = base.x - p.x, dy = base.y - p.y;
            const float dz = base.z - p.z, dw = base.w - p.w;
            V[s]     = dx * f.x + dy * f.y + dz * f.z + dw * f.w;
            V[8 + s] = dx * dx  + dy * dy  + dz * dz  + dw * dw;
        }
        #pragma unroll
        for (int m = 16, cnt = 16; m >= 2; m >>= 1, cnt >>= 1) {
            const int  half  = cnt >> 1;
            const bool upper = (lane & m) != 0;
            #pragma unroll
            for (int j = 0; j < 8; ++j) {
                if (j < half) {
                    float send = upper ? V[j] : V[j + half];
                    float recv = __shfl_xor_sync(FULL, send, m);
                    V[j] = (upper ? V[j + half] : V[j]) + recv;
                }
            }
        }
        D2 = V[0] + __shfl_xor_sync(FULL, V[0], 1);
    }

    // Lanes 16..31 hold squared norms; hand them to lanes 0..15.
    const float M1 = __shfl_xor_sync(FULL, D1, 16);
    const float M2 = __shfl_xor_sync(FULL, D2, 16);

    // Even lanes (<16) own pass-1 sample (l>>1); odd own pass-2 sample 8+(l>>1).
    const int  odd  = lane & 1;
    const int  samp = (lane >> 1) | (odd ? 8 : 0);
    const float ev  = __shfl_sync(FULL, ev_own, samp);

    float a, logit;
    if (lane < 16) {
        const float dot = odd ? D2 : D1;
        const float n2  = odd ? M2 : M1;
        logit = dot + u * ev;
        a = 1.0f - sqrtf(n2);
    } else {
        logit = 0.f;
        a = -1e30f;
    }

    // 16-wide softmax among lanes 0..15
    float mx = a;
    #pragma unroll
    for (int o = 8; o > 0; o >>= 1)
        mx = fmaxf(mx, __shfl_xor_sync(FULL, mx, o));

    const float e = (lane < 16) ? __expf(a - mx) : 0.f;
    float num = logit * e;
    float den = e;
    #pragma unroll
    for (int o = 8; o > 0; o >>= 1) {
        num += __shfl_xor_sync(FULL, num, o);
        den += __shfl_xor_sync(FULL, den, o);
    }

    if (lane == 0) out[n] = num / den;
}

extern "C" void kernel_launch(void* const* d_in, const int* in_sizes, int n_in,
                              void* d_out, int out_size)
{
    const int*   src      = (const int*)  d_in[0];
    const int*   dst      = (const int*)  d_in[1];
    const int*   mid0     = (const int*)  d_in[2];
    const int*   mid1     = (const int*)  d_in[3];
    const float* position = (const float*)d_in[4];
    const float* src_f    = (const float*)d_in[5];
    const float* dst_f    = (const float*)d_in[6];
    const float* unc      = (const float*)d_in[7];
    const float* edge     = (const float*)d_in[8];
    float*       out      = (float*)      d_out;

    // Prologue: fp32 -> fp16 tables (stream-ordered before main kernel)
    cvt_kernel<<<(N_NODES * 32 + 255) / 256, 256>>>(position, src_f, dst_f);

    const int blocks = NQUERY / 8;   // 8 warps (queries) per 256-thread block
    madgraph_kernel<<<blocks, 256>>>(src, dst, mid0, mid1, position,
                                     src_f, dst_f, unc, edge, out);
}

// round 13
// speedup vs baseline: 1.3712x; 1.0803x over previous
#include <cuda_runtime.h>
#include <cuda_fp16.h>
#include <cuda_bf16.h>

#define N_NODES 10000
#define NQUERY  65536

// fp16 copies of the three node tables, rebuilt each launch (7.5 MB, L2-resident)
__device__ __half2 g_posh[N_NODES * 64];
__device__ __half2 g_sfh [N_NODES * 64];
__device__ __half2 g_dfh [N_NODES * 64];

__global__ __launch_bounds__(256)
void cvt_kernel(const float* __restrict__ position,
                const float* __restrict__ src_field,
                const float* __restrict__ dst_field)
{
    const int i = blockIdx.x * blockDim.x + threadIdx.x;   // one float4 per thread
    if (i < N_NODES * 32) {
        float4 v = __ldg(&((const float4*)position)[i]);
        g_posh[i * 2 + 0] = __floats2half2_rn(v.x, v.y);
        g_posh[i * 2 + 1] = __floats2half2_rn(v.z, v.w);
        v = __ldg(&((const float4*)src_field)[i]);
        g_sfh[i * 2 + 0] = __floats2half2_rn(v.x, v.y);
        g_sfh[i * 2 + 1] = __floats2half2_rn(v.z, v.w);
        v = __ldg(&((const float4*)dst_field)[i]);
        g_dfh[i * 2 + 0] = __floats2half2_rn(v.x, v.y);
        g_dfh[i * 2 + 1] = __floats2half2_rn(v.z, v.w);
    }
}

__global__ __launch_bounds__(256, 6)
void madgraph_kernel(const int* __restrict__ src,
                     const int* __restrict__ dst,
                     const int* __restrict__ mid0,
                     const int* __restrict__ mid1,
                     const float* __restrict__ position,
                     const float* __restrict__ src_field,
                     const float* __restrict__ dst_field,
                     const float* __restrict__ unc,
                     const float* __restrict__ edge,
                     float* __restrict__ out)
{
    const unsigned FULL = 0xFFFFFFFFu;
    const int warp = (blockIdx.x * blockDim.x + threadIdx.x) >> 5;
    const int lane = threadIdx.x & 31;
    const int n = warp;

    const int s_node = __ldg(&src[n]);
    const int d_node = __ldg(&dst[n]);

    // Lane l<8 holds mid0[n][l]; lanes 8..15 hold mid1[n][l-8].
    int m_own = 0;
    if (lane < 8)        m_own = __ldg(&mid0[n * 8 + lane]);
    else if (lane < 16)  m_own = __ldg(&mid1[n * 8 + (lane - 8)]);

    // Edge value (400MB DRAM table): evict-first so it never displaces the
    // hot fp16 tables in L2. Issue ASAP; consumed at the very end.
    float ev_own = 0.f;
    if (lane < 16) {
        const int eidx = (lane < 8) ? (m_own * N_NODES + d_node)    // edge[mid0[s], dst]
                                    : (s_node * N_NODES + m_own);   // edge[src, mid1[s]]
        ev_own = __ldcs(&edge[eidx]);
    }
    const float u = __ldg(unc);

    // fp16 rows: lane owns dims [4*lane..4*lane+3] = two half2 (8B)
    const __half2* posh = g_posh;
    const __half2* sfh  = g_sfh;
    const __half2* dfh  = g_dfh;

    float D1, D2;

    // ---- pass 1: samples 0..7 (base = pos[src], field = dst_field[dst]) ----
    {
        const __half2 b01 = posh[s_node * 64 + lane * 2];
        const __half2 b23 = posh[s_node * 64 + lane * 2 + 1];
        const __half2 f01 = dfh [d_node * 64 + lane * 2];
        const __half2 f23 = dfh [d_node * 64 + lane * 2 + 1];
        int mm[8];
        #pragma unroll
        for (int s = 0; s < 8; ++s) mm[s] = __shfl_sync(FULL, m_own, s);
        __half2 pm[16];
        #pragma unroll
        for (int s = 0; s < 8; ++s) {
            const uint2 r = *(const uint2*)&posh[mm[s] * 64 + lane * 2];
            pm[2 * s]     = *(const __half2*)&r.x;
            pm[2 * s + 1] = *(const __half2*)&r.y;
        }
        float V[16];
        #pragma unroll
        for (int s = 0; s < 8; ++s) {
            const __half2 d01 = __hsub2(b01, pm[2 * s]);
            const __half2 d23 = __hsub2(b23, pm[2 * s + 1]);
            const __half2 dh  = __hfma2(d23, f23, __hmul2(d01, f01));
            const __half2 nh  = __hfma2(d23, d23, __hmul2(d01, d01));
            const float2 df = __half22float2(dh);
            const float2 nf = __half22float2(nh);
            V[s]     = df.x + df.y;
            V[8 + s] = nf.x + nf.y;
        }
        #pragma unroll
        for (int m = 16, cnt = 16; m >= 2; m >>= 1, cnt >>= 1) {
            const int  half  = cnt >> 1;
            const bool upper = (lane & m) != 0;
            #pragma unroll
            for (int j = 0; j < 8; ++j) {
                if (j < half) {
                    float send = upper ? V[j] : V[j + half];
                    float recv = __shfl_xor_sync(FULL, send, m);
                    V[j] = (upper ? V[j + half] : V[j]) + recv;
                }
            }
        }
        D1 = V[0] + __shfl_xor_sync(FULL, V[0], 1);
    }

    // ---- pass 2: samples 8..15 (base = pos[dst], field = src_field[src]) ----
    {
        const __half2 b01 = posh[d_node * 64 + lane * 2];
        const __half2 b23 = posh[d_node * 64 + lane * 2 + 1];
        const __half2 f01 = sfh [s_node * 64 + lane * 2];
        const __half2 f23 = sfh [s_node * 64 + lane * 2 + 1];
        int mm[8];
        #pragma unroll
        for (int s = 0; s < 8; ++s) mm[s] = __shfl_sync(FULL, m_own, 8 + s);
        __half2 pm[16];
        #pragma unroll
        for (int s = 0; s < 8; ++s) {
            const uint2 r = *(const uint2*)&posh[mm[s] * 64 + lane * 2];
            pm[2 * s]     = *(const __half2*)&r.x;
            pm[2 * s + 1] = *(const __half2*)&r.y;
        }
        float V[16];
        #pragma unroll
        for (int s = 0; s < 8; ++s) {
            const __half2 d01 = __hsub2(b01, pm[2 * s]);
            const __half2 d23 = __hsub2(b23, pm[2 * s + 1]);
            const __half2 dh  = __hfma2(d23, f23, __hmul2(d01, f01));
            const __half2 nh  = __hfma2(d23, d23, __hmul2(d01, d01));
            const float2 df = __half22float2(dh);
            const float2 nf = __half22float2(nh);
            V[s]     = df.x + df.y;
            V[8 + s] = nf.x + nf.y;
        }
        #pragma unroll
        for (int m = 16, cnt = 16; m >= 2; m >>= 1, cnt >>= 1) {
            const int  half  = cnt >> 1;
            const bool upper = (lane & m) != 0;
            #pragma unroll
            for (int j = 0; j < 8; ++j) {
                if (j < half) {
                    float send = upper ? V[j] : V[j + half];
                    float recv = __shfl_xor_sync(FULL, send, m);
                    V[j] = (upper ? V[j + half] : V[j]) + recv;
                }
            }
        }
        D2 = V[0] + __shfl_xor_sync(FULL, V[0], 1);
    }

    // Lanes 16..31 hold squared norms; hand them to lanes 0..15.
    const float M1 = __shfl_xor_sync(FULL, D1, 16);
    const float M2 = __shfl_xor_sync(FULL, D2, 16);

    // Even lanes (<16) own pass-1 sample (l>>1); odd own pass-2 sample 8+(l>>1).
    const int  odd  = lane & 1;
    const int  samp = (lane >> 1) | (odd ? 8 : 0);
    const float ev  = __shfl_sync(FULL, ev_own, samp);

    float a, logit;
    if (lane < 16) {
        const float dot = odd ? D2 : D1;
        const float n2  = odd ? M2 : M1;
        logit = dot + u * ev;
        a = 1.0f - sqrtf(n2);
    } else {
        logit = 0.f;
        a = -1e30f;
    }

    // 16-wide softmax among lanes 0..15
    float mx = a;
    #pragma unroll
    for (int o = 8; o > 0; o >>= 1)
        mx = fmaxf(mx, __shfl_xor_sync(FULL, mx, o));

    const float e = (lane < 16) ? __expf(a - mx) : 0.f;
    float num = logit * e;
    float den = e;
    #pragma unroll
    for (int o = 8; o > 0; o >>= 1) {
        num += __shfl_xor_sync(FULL, num, o);
        den += __shfl_xor_sync(FULL, den, o);
    }

    if (lane == 0) out[n] = num / den;
}

extern "C" void kernel_launch(void* const* d_in, const int* in_sizes, int n_in,
                              void* d_out, int out_size)
{
    const int*   src      = (const int*)  d_in[0];
    const int*   dst      = (const int*)  d_in[1];
    const int*   mid0     = (const int*)  d_in[2];
    const int*   mid1     = (const int*)  d_in[3];
    const float* position = (const float*)d_in[4];
    const float* src_f    = (const float*)d_in[5];
    const float* dst_f    = (const float*)d_in[6];
    const float* unc      = (const float*)d_in[7];
    const float* edge     = (const float*)d_in[8];
    float*       out      = (float*)      d_out;

    // Prologue: fp32 -> fp16 tables (stream-ordered before main kernel)
    cvt_kernel<<<(N_NODES * 32 + 255) / 256, 256>>>(position, src_f, dst_f);

    const int blocks = NQUERY / 8;   // 8 warps (queries) per 256-thread block
    madgraph_kernel<<<blocks, 256>>>(src, dst, mid0, mid1, position,
                                     src_f, dst_f, unc, edge, out);
}

// round 14
// speedup vs baseline: 1.3777x; 1.0047x over previous
#include <cuda_runtime.h>
#include <cuda_fp16.h>
#include <cuda_bf16.h>

#define N_NODES 10000
#define NQUERY  65536

// fp16 copies of the three node tables, rebuilt each launch (7.5 MB, L2-resident)
__device__ __half2 g_posh[N_NODES * 64];
__device__ __half2 g_sfh [N_NODES * 64];
__device__ __half2 g_dfh [N_NODES * 64];

__global__ __launch_bounds__(256)
void cvt_kernel(const float* __restrict__ position,
                const float* __restrict__ src_field,
                const float* __restrict__ dst_field)
{
    const int i = blockIdx.x * blockDim.x + threadIdx.x;   // one float4 per thread
    if (i < N_NODES * 32) {
        float4 v = __ldg(&((const float4*)position)[i]);
        g_posh[i * 2 + 0] = __floats2half2_rn(v.x, v.y);
        g_posh[i * 2 + 1] = __floats2half2_rn(v.z, v.w);
        v = __ldg(&((const float4*)src_field)[i]);
        g_sfh[i * 2 + 0] = __floats2half2_rn(v.x, v.y);
        g_sfh[i * 2 + 1] = __floats2half2_rn(v.z, v.w);
        v = __ldg(&((const float4*)dst_field)[i]);
        g_dfh[i * 2 + 0] = __floats2half2_rn(v.x, v.y);
        g_dfh[i * 2 + 1] = __floats2half2_rn(v.z, v.w);
    }
}

__device__ __forceinline__ __half2 shfl_xor_h2(unsigned mask, __half2 v, int m)
{
    unsigned u = *(unsigned*)&v;
    u = __shfl_xor_sync(mask, u, m);
    return *(__half2*)&u;
}

__global__ __launch_bounds__(256, 6)
void madgraph_kernel(const int* __restrict__ src,
                     const int* __restrict__ dst,
                     const int* __restrict__ mid0,
                     const int* __restrict__ mid1,
                     const float* __restrict__ position,
                     const float* __restrict__ src_field,
                     const float* __restrict__ dst_field,
                     const float* __restrict__ unc,
                     const float* __restrict__ edge,
                     float* __restrict__ out)
{
    const unsigned FULL = 0xFFFFFFFFu;
    const int warp = (blockIdx.x * blockDim.x + threadIdx.x) >> 5;
    const int lane = threadIdx.x & 31;
    const int n = warp;

    const int s_node = __ldg(&src[n]);
    const int d_node = __ldg(&dst[n]);

    // Lane l<8 holds mid0[n][l]; lanes 8..15 hold mid1[n][l-8].
    int m_own = 0;
    if (lane < 8)        m_own = __ldg(&mid0[n * 8 + lane]);
    else if (lane < 16)  m_own = __ldg(&mid1[n * 8 + (lane - 8)]);

    // Edge value (400MB DRAM table): evict-first, issue ASAP.
    float ev_own = 0.f;
    if (lane < 16) {
        const int eidx = (lane < 8) ? (m_own * N_NODES + d_node)    // edge[mid0[s], dst]
                                    : (s_node * N_NODES + m_own);   // edge[src, mid1[s]]
        ev_own = __ldcs(&edge[eidx]);
    }
    const float u = __ldg(unc);

    const __half2* posh = g_posh;
    const __half2* sfh  = g_sfh;
    const __half2* dfh  = g_dfh;

    // H[v] = packed (dot_partial, n2_partial) for sample v (0..7 pass1, 8..15 pass2)
    __half2 H[16];

    // ---- pass 1: samples 0..7 (base = pos[src], field = dst_field[dst]) ----
    {
        const uint2 br = *(const uint2*)&posh[s_node * 64 + lane * 2];
        const uint2 fr = *(const uint2*)&dfh [d_node * 64 + lane * 2];
        const __half2 b01 = *(const __half2*)&br.x, b23 = *(const __half2*)&br.y;
        const __half2 f01 = *(const __half2*)&fr.x, f23 = *(const __half2*)&fr.y;
        int mm[8];
        #pragma unroll
        for (int s = 0; s < 8; ++s) mm[s] = __shfl_sync(FULL, m_own, s);
        uint2 pm[8];
        #pragma unroll
        for (int s = 0; s < 8; ++s) pm[s] = *(const uint2*)&posh[mm[s] * 64 + lane * 2];
        #pragma unroll
        for (int s = 0; s < 8; ++s) {
            const __half2 d01 = __hsub2(b01, *(const __half2*)&pm[s].x);
            const __half2 d23 = __hsub2(b23, *(const __half2*)&pm[s].y);
            const __half2 dh  = __hfma2(d23, f23, __hmul2(d01, f01));
            const __half2 nh  = __hfma2(d23, d23, __hmul2(d01, d01));
            H[s] = __hadd2(__lows2half2(dh, nh), __highs2half2(dh, nh));
        }
    }

    // ---- pass 2: samples 8..15 (base = pos[dst], field = src_field[src]) ----
    {
        const uint2 br = *(const uint2*)&posh[d_node * 64 + lane * 2];
        const uint2 fr = *(const uint2*)&sfh [s_node * 64 + lane * 2];
        const __half2 b01 = *(const __half2*)&br.x, b23 = *(const __half2*)&br.y;
        const __half2 f01 = *(const __half2*)&fr.x, f23 = *(const __half2*)&fr.y;
        int mm[8];
        #pragma unroll
        for (int s = 0; s < 8; ++s) mm[s] = __shfl_sync(FULL, m_own, 8 + s);
        uint2 pm[8];
        #pragma unroll
        for (int s = 0; s < 8; ++s) pm[s] = *(const uint2*)&posh[mm[s] * 64 + lane * 2];
        #pragma unroll
        for (int s = 0; s < 8; ++s) {
            const __half2 d01 = __hsub2(b01, *(const __half2*)&pm[s].x);
            const __half2 d23 = __hsub2(b23, *(const __half2*)&pm[s].y);
            const __half2 dh  = __hfma2(d23, f23, __hmul2(d01, f01));
            const __half2 nh  = __hfma2(d23, d23, __hmul2(d01, d01));
            H[8 + s] = __hadd2(__lows2half2(dh, nh), __highs2half2(dh, nh));
        }
    }

    // ---- single packed butterfly over all 16 samples ----
    // Packed stages m=16,8,4 (partial sums small -> fp16 safe):
    #pragma unroll
    for (int m = 16, cnt = 16; m >= 4; m >>= 1, cnt >>= 1) {
        const int  half  = cnt >> 1;
        const bool upper = (lane & m) != 0;
        #pragma unroll
        for (int j = 0; j < 8; ++j) {
            if (j < half) {
                __half2 send = upper ? H[j] : H[j + half];
                __half2 recv = shfl_xor_h2(FULL, send, m);
                H[j] = __hadd2(upper ? H[j + half] : H[j], recv);
            }
        }
    }
    // Unpack to fp32 for the last two stages (values get large here).
    float2 A = __half22float2(H[0]);   // candidate value idx +0
    float2 B = __half22float2(H[1]);   // candidate value idx +1
    float d, nn;
    {
        const bool up2 = (lane & 2) != 0;
        const float sd = up2 ? A.x : B.x;
        const float sn = up2 ? A.y : B.y;
        const float rd = __shfl_xor_sync(FULL, sd, 2);
        const float rn = __shfl_xor_sync(FULL, sn, 2);
        d  = (up2 ? B.x : A.x) + rd;
        nn = (up2 ? B.y : A.y) + rn;
        d  += __shfl_xor_sync(FULL, d,  1);
        nn += __shfl_xor_sync(FULL, nn, 1);
    }
    // Lane l now holds (dot, n2) totals for sample l>>1.

    // Sample s lives at lane 2s; ev_own for sample s lives at lane s.
    const float dot_s = __shfl_sync(FULL, d,  lane * 2);
    const float n2_s  = __shfl_sync(FULL, nn, lane * 2);

    float a, logit;
    if (lane < 16) {
        logit = dot_s + u * ev_own;
        a = 1.0f - sqrtf(n2_s);
    } else {
        logit = 0.f;
        a = -1e30f;
    }

    // 16-wide softmax among lanes 0..15
    float mx = a;
    #pragma unroll
    for (int o = 8; o > 0; o >>= 1)
        mx = fmaxf(mx, __shfl_xor_sync(FULL, mx, o));

    const float e = (lane < 16) ? __expf(a - mx) : 0.f;
    float num = logit * e;
    float den = e;
    #pragma unroll
    for (int o = 8; o > 0; o >>= 1) {
        num += __shfl_xor_sync(FULL, num, o);
        den += __shfl_xor_sync(FULL, den, o);
    }

    if (lane == 0) out[n] = num / den;
}

extern "C" void kernel_launch(void* const* d_in, const int* in_sizes, int n_in,
                              void* d_out, int out_size)
{
    const int*   src      = (const int*)  d_in[0];
    const int*   dst      = (const int*)  d_in[1];
    const int*   mid0     = (const int*)  d_in[2];
    const int*   mid1     = (const int*)  d_in[3];
    const float* position = (const float*)d_in[4];
    const float* src_f    = (const float*)d_in[5];
    const float* dst_f    = (const float*)d_in[6];
    const float* unc      = (const float*)d_in[7];
    const float* edge     = (const float*)d_in[8];
    float*       out      = (float*)      d_out;

    // Prologue: fp32 -> fp16 tables (stream-ordered before main kernel)
    cvt_kernel<<<(N_NODES * 32 + 255) / 256, 256>>>(position, src_f, dst_f);

    const int blocks = NQUERY / 8;   // 8 warps (queries) per 256-thread block
    madgraph_kernel<<<blocks, 256>>>(src, dst, mid0, mid1, position,
                                     src_f, dst_f, unc, edge, out);
}

// round 15
// speedup vs baseline: 1.3908x; 1.0095x over previous
#include <cuda_runtime.h>
#include <cuda_fp16.h>
#include <cuda_bf16.h>

#define N_NODES 10000
#define NQUERY  65536

// fp16 copies of the three node tables, rebuilt each launch (7.5 MB, L2-resident)
__device__ __half2 g_posh[N_NODES * 64];
__device__ __half2 g_sfh [N_NODES * 64];
__device__ __half2 g_dfh [N_NODES * 64];

__global__ __launch_bounds__(256)
void cvt_kernel(const float* __restrict__ position,
                const float* __restrict__ src_field,
                const float* __restrict__ dst_field)
{
    const int i = blockIdx.x * blockDim.x + threadIdx.x;   // one float4 per thread
    if (i < N_NODES * 32) {
        float4 v = __ldg(&((const float4*)position)[i]);
        g_posh[i * 2 + 0] = __floats2half2_rn(v.x, v.y);
        g_posh[i * 2 + 1] = __floats2half2_rn(v.z, v.w);
        v = __ldg(&((const float4*)src_field)[i]);
        g_sfh[i * 2 + 0] = __floats2half2_rn(v.x, v.y);
        g_sfh[i * 2 + 1] = __floats2half2_rn(v.z, v.w);
        v = __ldg(&((const float4*)dst_field)[i]);
        g_dfh[i * 2 + 0] = __floats2half2_rn(v.x, v.y);
        g_dfh[i * 2 + 1] = __floats2half2_rn(v.z, v.w);
    }
}

#define H2REF(x) (*(const __half2*)&(x))

__device__ __forceinline__ __half2 shfl_xor_h2(unsigned mask, __half2 v, int m)
{
    unsigned u = *(unsigned*)&v;
    u = __shfl_xor_sync(mask, u, m);
    return *(__half2*)&u;
}

// packed (dot_partial, n2_partial) over this lane's 8 dims
__device__ __forceinline__ __half2 sample_h(const uint4& b, const uint4& f, const uint4& p)
{
    const __half2 d0 = __hsub2(H2REF(b.x), H2REF(p.x));
    const __half2 d1 = __hsub2(H2REF(b.y), H2REF(p.y));
    const __half2 d2 = __hsub2(H2REF(b.z), H2REF(p.z));
    const __half2 d3 = __hsub2(H2REF(b.w), H2REF(p.w));
    __half2 dh = __hmul2(d0, H2REF(f.x));
    dh = __hfma2(d1, H2REF(f.y), dh);
    dh = __hfma2(d2, H2REF(f.z), dh);
    dh = __hfma2(d3, H2REF(f.w), dh);
    __half2 nh = __hmul2(d0, d0);
    nh = __hfma2(d1, d1, nh);
    nh = __hfma2(d2, d2, nh);
    nh = __hfma2(d3, d3, nh);
    return __hadd2(__lows2half2(dh, nh), __highs2half2(dh, nh));
}

__global__ __launch_bounds__(256, 5)
void madgraph_kernel(const int* __restrict__ src,
                     const int* __restrict__ dst,
                     const int* __restrict__ mid0,
                     const int* __restrict__ mid1,
                     const float* __restrict__ position,
                     const float* __restrict__ src_field,
                     const float* __restrict__ dst_field,
                     const float* __restrict__ unc,
                     const float* __restrict__ edge,
                     float* __restrict__ out)
{
    const unsigned FULL = 0xFFFFFFFFu;
    const int warp = (blockIdx.x * blockDim.x + threadIdx.x) >> 5;
    const int lane = threadIdx.x & 31;
    const int hl   = lane & 15;          // lane within half-warp
    const int hsel = lane & 16;          // 0 = query A, 16 = query B
    const int n    = warp * 2 + (hsel >> 4);

    const int s_node = __ldg(&src[n]);
    const int d_node = __ldg(&dst[n]);

    // Every lane owns one sample of its query: hl<8 -> mid0[hl], else mid1[hl-8].
    const int m_own = (hl < 8) ? __ldg(&mid0[n * 8 + hl])
                               : __ldg(&mid1[n * 8 + (hl - 8)]);

    // Edge value (400MB DRAM table): evict-first, issue ASAP.
    const int eidx = (hl < 8) ? (m_own * N_NODES + d_node)    // edge[mid0[s], dst]
                              : (s_node * N_NODES + m_own);   // edge[src, mid1[s]]
    const float ev = __ldcs(&edge[eidx]);
    const float u  = __ldg(unc);

    // Row m of a table = uint4 indices [m*16 .. m*16+15]; lane owns dims [8*hl..8*hl+7].
    const uint4* posh4 = (const uint4*)g_posh;
    const uint4* sfh4  = (const uint4*)g_sfh;
    const uint4* dfh4  = (const uint4*)g_dfh;

    __half2 H1[8], G[8];

    // ---- pass 1: samples 0..7 (base = pos[src], field = dst_field[dst]) ----
    {
        const uint4 b = posh4[s_node * 16 + hl];
        const uint4 f = dfh4 [d_node * 16 + hl];
        #pragma unroll
        for (int c = 0; c < 2; ++c) {
            int mm[4]; uint4 pm[4];
            #pragma unroll
            for (int j = 0; j < 4; ++j)
                mm[j] = __shfl_sync(FULL, m_own, (c * 4 + j) + hsel);
            #pragma unroll
            for (int j = 0; j < 4; ++j)
                pm[j] = posh4[mm[j] * 16 + hl];
            #pragma unroll
            for (int j = 0; j < 4; ++j)
                H1[c * 4 + j] = sample_h(b, f, pm[j]);
        }
    }

    // ---- pass 2: samples 8..15 (base = pos[dst], field = src_field[src]) ----
    {
        const uint4 b = posh4[d_node * 16 + hl];
        const uint4 f = sfh4 [s_node * 16 + hl];
        #pragma unroll
        for (int c = 0; c < 2; ++c) {
            int mm[4]; uint4 pm[4];
            #pragma unroll
            for (int j = 0; j < 4; ++j)
                mm[j] = __shfl_sync(FULL, m_own, (8 + c * 4 + j) + hsel);
            #pragma unroll
            for (int j = 0; j < 4; ++j)
                pm[j] = posh4[mm[j] * 16 + hl];
            #pragma unroll
            for (int j = 0; j < 4; ++j)
                G[c * 4 + j] = sample_h(b, f, pm[j]);
        }
    }

    // ---- 16-value butterfly within each 16-lane half (identity mapping) ----
    // Stage m=8 fused with the pass1/pass2 merge: value index bit3 = lane bit3.
    __half2 Hc[8];
    {
        const bool up = (lane & 8) != 0;
        #pragma unroll
        for (int j = 0; j < 8; ++j) {
            const __half2 send = up ? H1[j] : G[j];
            const __half2 keep = up ? G[j] : H1[j];
            Hc[j] = __hadd2(keep, shfl_xor_h2(FULL, send, 8));
        }
    }
    // Stage m=4 (packed fp16; partial sums still small)
    {
        const bool up = (lane & 4) != 0;
        #pragma unroll
        for (int j = 0; j < 4; ++j) {
            const __half2 send = up ? Hc[j] : Hc[j + 4];
            const __half2 keep = up ? Hc[j + 4] : Hc[j];
            Hc[j] = __hadd2(keep, shfl_xor_h2(FULL, send, 4));
        }
    }
    // Unpack to fp32 for the last two stages (values get large).
    float2 F[4];
    #pragma unroll
    for (int j = 0; j < 4; ++j) F[j] = __half22float2(Hc[j]);
    {
        const bool up = (lane & 2) != 0;
        #pragma unroll
        for (int j = 0; j < 2; ++j) {
            const float sx = up ? F[j].x : F[j + 2].x;
            const float sy = up ? F[j].y : F[j + 2].y;
            const float kx = up ? F[j + 2].x : F[j].x;
            const float ky = up ? F[j + 2].y : F[j].y;
            F[j].x = kx + __shfl_xor_sync(FULL, sx, 2);
            F[j].y = ky + __shfl_xor_sync(FULL, sy, 2);
        }
    }
    {
        const bool up = (lane & 1) != 0;
        const float sx = up ? F[0].x : F[1].x;
        const float sy = up ? F[0].y : F[1].y;
        const float kx = up ? F[1].x : F[0].x;
        const float ky = up ? F[1].y : F[0].y;
        F[0].x = kx + __shfl_xor_sync(FULL, sx, 1);
        F[0].y = ky + __shfl_xor_sync(FULL, sy, 1);
    }
    // Lane hl of each half now holds sample hl's (dot, n2); ev is already here.
    const float dot = F[0].x;
    const float n2  = F[0].y;

    const float logit = dot + u * ev;
    const float a     = 1.0f - sqrtf(n2);

    // 16-wide softmax within each half (offsets 8..1 stay inside the half).
    float mx = a;
    #pragma unroll
    for (int o = 8; o > 0; o >>= 1)
        mx = fmaxf(mx, __shfl_xor_sync(FULL, mx, o));

    const float e = __expf(a - mx);
    float num = logit * e;
    float den = e;
    #pragma unroll
    for (int o = 8; o > 0; o >>= 1) {
        num += __shfl_xor_sync(FULL, num, o);
        den += __shfl_xor_sync(FULL, den, o);
    }

    if (hl == 0) out[n] = num / den;
}

extern "C" void kernel_launch(void* const* d_in, const int* in_sizes, int n_in,
                              void* d_out, int out_size)
{
    const int*   src      = (const int*)  d_in[0];
    const int*   dst      = (const int*)  d_in[1];
    const int*   mid0     = (const int*)  d_in[2];
    const int*   mid1     = (const int*)  d_in[3];
    const float* position = (const float*)d_in[4];
    const float* src_f    = (const float*)d_in[5];
    const float* dst_f    = (const float*)d_in[6];
    const float* unc      = (const float*)d_in[7];
    const float* edge     = (const float*)d_in[8];
    float*       out      = (float*)      d_out;

    // Prologue: fp32 -> fp16 tables (stream-ordered before main kernel)
    cvt_kernel<<<(N_NODES * 32 + 255) / 256, 256>>>(position, src_f, dst_f);

    const int blocks = NQUERY / 16;  // 8 warps x 2 queries per 256-thread block
    madgraph_kernel<<<blocks, 256>>>(src, dst, mid0, mid1, position,
                                     src_f, dst_f, unc, edge, out);
}